// round 13
// baseline (speedup 1.0000x reference)
#include <cuda_runtime.h>
#include <cuda_bf16.h>

// Problem constants
#define Bsz   64
#define Tsz   512
#define Kdim  1024     // IN_DIM
#define Hdim  1024     // HID
#define Mdim  (Bsz * Tsz)   // 32768 rows of the GEMM

// exp(-1/20); compiler rounds to nearest f32, same as XLA's f64->f32 constant
#define ALPHA_F 0.95122942450071400910f
#define THRESH_F 1.0f

// Eigen gebp K-panel size (computeProductBlockingSizes caps kc at 320)
#define KC 320

// 128 MB scratch for the pre-activation currents I[b,t,h]
__device__ float g_I[(size_t)Mdim * Hdim];

// ---------------------------------------------------------------------------
// Packed f32x2 helpers. Each half of fma.rn.f32x2 / add.rn.f32x2 is an
// independent IEEE-754 fp32 fma.rn / add.rn -> bit-identical to the scalar
// ops of the validated rounding contract. (Measured R12: FFMA2 retires
// 2 FMA / ~4 SMSP-cyc = same FMA rate as scalar, but halves issue slots.)
// ---------------------------------------------------------------------------
typedef unsigned long long u64;

__device__ __forceinline__ u64 pack2(float x, float y) {
    u64 r; asm("mov.b64 %0, {%1, %2};" : "=l"(r) : "f"(x), "f"(y)); return r;
}
__device__ __forceinline__ void unpack2(u64 v, float& x, float& y) {
    asm("mov.b64 {%0, %1}, %2;" : "=f"(x), "=f"(y) : "l"(v));
}
__device__ __forceinline__ void ffma2(u64& d, u64 a, u64 b) {
    asm("fma.rn.f32x2 %0, %1, %2, %0;" : "+l"(d) : "l"(a), "l"(b));
}
__device__ __forceinline__ void fadd2(u64& d, u64 a) {
    asm("add.rn.f32x2 %0, %0, %1;" : "+l"(d) : "l"(a));
}

// ---------------------------------------------------------------------------
// GEMM: I[m,n] = sum_k x[m,k] * W[n,k] + bias[n]   ("NT", both K-contiguous)
//
// ROUNDING CONTRACT (validated bit-exact in R9, rel_err 4e-7 -- DO NOT CHANGE):
//   per output element:
//     c0..c3 = natural-order fma chains over k-panels {0..319, 320..639,
//              640..959, 960..1023}, each starting from 0
//     total  = (((0 + c0) + c1) + c2) + c3     [plain fp32 adds, in order]
//     I      = total + bias                     [one add at the end]
//
// 128x128 block tile, 8x8 micro-tile (8x4 packed n-pairs), BK=8,
// register prefetch + DOUBLE-BUFFERED smem -> one __syncthreads per tile.
// ---------------------------------------------------------------------------
#define BM 128
#define BN 128
#define BK 8
#define TM 8
#define TN 8
#define TN2 (TN / 2)
#define SPAD 4   // smem padding to kill store bank conflicts

__global__ __launch_bounds__(256, 1)
void snn_gemm_kernel(const float* __restrict__ A,      // [M, K] = x
                     const float* __restrict__ Bmat,   // [N, K] = W
                     const float* __restrict__ bias,   // [N]
                     float* __restrict__ C)            // [M, N] = I
{
    __shared__ float As[2][BK][BM + SPAD];
    __shared__ float Bs[2][BK][BN + SPAD];

    const int tid = threadIdx.x;
    const int bm  = blockIdx.y * BM;
    const int bn  = blockIdx.x * BN;

    const float* Ablk = A    + (size_t)bm * Kdim;
    const float* Bblk = Bmat + (size_t)bn * Kdim;

    // Load assignment: 2 threads per row, each loads one float4 of K.
    const int l_row = tid >> 1;           // 0..127
    const int l_col = (tid & 1) * 4;      // 0 or 4

    // Compute mapping: 16x16 thread grid; 8 rows x 8 cols per thread.
    const int tx = tid & 15;              // col group: 16 * 8 = 128 cols
    const int ty = tid >> 4;              // row group: 16 * 8 = 128 rows

    u64 acc2[TM][TN2];    // current K-panel chains (packed pairs of n)
    u64 tot2[TM][TN2];    // running sums of completed panels
#pragma unroll
    for (int i = 0; i < TM; i++)
#pragma unroll
        for (int j = 0; j < TN2; j++) { acc2[i][j] = 0ULL; tot2[i][j] = 0ULL; }

    const float* aptr = Ablk + (size_t)l_row * Kdim + l_col;
    const float* bptr = Bblk + (size_t)l_row * Kdim + l_col;

    // Load tile 0, commit to buffer 0.
    {
        float4 av = *(const float4*)(aptr);
        float4 bv = *(const float4*)(bptr);
        As[0][l_col + 0][l_row] = av.x;
        As[0][l_col + 1][l_row] = av.y;
        As[0][l_col + 2][l_row] = av.z;
        As[0][l_col + 3][l_row] = av.w;
        Bs[0][l_col + 0][l_row] = bv.x;
        Bs[0][l_col + 1][l_row] = bv.y;
        Bs[0][l_col + 2][l_row] = bv.z;
        Bs[0][l_col + 3][l_row] = bv.w;
    }
    __syncthreads();

    int p = 0;
    for (int k0 = 0; k0 < Kdim; k0 += BK) {
        const bool has_next = (k0 + BK) < Kdim;

        // Prefetch next tile into registers (overlaps the compute below).
        float4 av, bv;
        if (has_next) {
            av = *(const float4*)(aptr + k0 + BK);
            bv = *(const float4*)(bptr + k0 + BK);
        }

        // Compute from current buffer.
#pragma unroll
        for (int k = 0; k < BK; k++) {
            u64 a2[TM];
#pragma unroll
            for (int i = 0; i < TM; i++) {
                const float ar = As[p][k][ty * TM + i];
                a2[i] = pack2(ar, ar);
            }
            u64 b2[TN2];
#pragma unroll
            for (int j = 0; j < TN2; j++)
                b2[j] = *reinterpret_cast<const u64*>(&Bs[p][k][tx * TN + 2 * j]);

#pragma unroll
            for (int i = 0; i < TM; i++)
#pragma unroll
                for (int j = 0; j < TN2; j++)
                    ffma2(acc2[i][j], a2[i], b2[j]);
        }

        // Fold at Eigen K-panel boundaries: k = 320, 640, 960, 1024.
        const int knext = k0 + BK;
        if (knext == KC || knext == 2 * KC || knext == 3 * KC || knext == Kdim) {
#pragma unroll
            for (int i = 0; i < TM; i++)
#pragma unroll
                for (int j = 0; j < TN2; j++) {
                    fadd2(tot2[i][j], acc2[i][j]);
                    acc2[i][j] = 0ULL;
                }
        }

        // Commit prefetched tile to the other buffer; single barrier per tile.
        if (has_next) {
            const int q = p ^ 1;
            As[q][l_col + 0][l_row] = av.x;
            As[q][l_col + 1][l_row] = av.y;
            As[q][l_col + 2][l_row] = av.z;
            As[q][l_col + 3][l_row] = av.w;
            Bs[q][l_col + 0][l_row] = bv.x;
            Bs[q][l_col + 1][l_row] = bv.y;
            Bs[q][l_col + 2][l_row] = bv.z;
            Bs[q][l_col + 3][l_row] = bv.w;
            __syncthreads();
            p = q;
        }
    }

    // Epilogue: add bias once at the end (matches reference's einsum + b).
#pragma unroll
    for (int i = 0; i < TM; i++) {
        const int row = bm + ty * TM + i;
        float* crow = C + (size_t)row * Hdim + bn + tx * TN;
        float o[TN];
#pragma unroll
        for (int j = 0; j < TN2; j++)
            unpack2(tot2[i][j], o[2 * j], o[2 * j + 1]);
#pragma unroll
        for (int j = 0; j < TN; j += 4) {
            float4 v;
            v.x = __fadd_rn(o[j + 0], bias[bn + tx * TN + j + 0]);
            v.y = __fadd_rn(o[j + 1], bias[bn + tx * TN + j + 1]);
            v.z = __fadd_rn(o[j + 2], bias[bn + tx * TN + j + 2]);
            v.w = __fadd_rn(o[j + 3], bias[bn + tx * TN + j + 3]);
            *(float4*)(crow + j) = v;
        }
    }
}

// ---------------------------------------------------------------------------
// LIF scan -- EXACT R11 version (measured 63 us; R12's ldcs/unroll-16 variant
// regressed 4x, do not reintroduce). float2 lanes, unroll 8, plain loads.
// ROUNDING CONTRACT: separate mul/add/sub per element.
// ---------------------------------------------------------------------------
#define SCAN_TPB 128

__global__ __launch_bounds__(SCAN_TPB)
void snn_scan_kernel(const float2* __restrict__ I2,
                     float2* __restrict__ spikes2,     // [B, T, H/2]
                     float2* __restrict__ memf2)       // [B, H/2]
{
    const int gid = blockIdx.x * SCAN_TPB + threadIdx.x;  // 0 .. B*H/2-1
    const int H2  = Hdim / 2;                              // 512
    const int b   = gid >> 9;        // / H2
    const int h2  = gid & (H2 - 1);

    const size_t base = ((size_t)b * Tsz) * H2 + h2;

    float mx = 0.0f, my = 0.0f;
#pragma unroll 8
    for (int t = 0; t < Tsz; t++) {
        const float2 cur = I2[base + (size_t)t * H2];

        const float ax = __fadd_rn(__fmul_rn(ALPHA_F, mx), cur.x);
        const float ay = __fadd_rn(__fmul_rn(ALPHA_F, my), cur.y);
        const float sx = (ax >= THRESH_F) ? 1.0f : 0.0f;
        const float sy = (ay >= THRESH_F) ? 1.0f : 0.0f;

        float2 sp; sp.x = sx; sp.y = sy;
        spikes2[base + (size_t)t * H2] = sp;

        mx = __fmul_rn(ax, __fsub_rn(1.0f, sx));
        my = __fmul_rn(ay, __fsub_rn(1.0f, sy));
    }
    float2 mf; mf.x = mx; mf.y = my;
    memf2[gid] = mf;
}

// ---------------------------------------------------------------------------
// Launch
// ---------------------------------------------------------------------------
extern "C" void kernel_launch(void* const* d_in, const int* in_sizes, int n_in,
                              void* d_out, int out_size)
{
    const float* x    = (const float*)d_in[0];   // [B, T, IN]
    const float* W    = (const float*)d_in[1];   // [H, IN]
    const float* bias = (const float*)d_in[2];   // [H]

    float* out        = (float*)d_out;
    float* spikes     = out;                                  // [B,T,H]
    float* mem_final  = out + (size_t)Mdim * Hdim;            // [B,H]

    float* I;
    cudaGetSymbolAddress((void**)&I, g_I);

    dim3 ggrid(Hdim / BN, Mdim / BM);   // (8, 256)
    snn_gemm_kernel<<<ggrid, 256>>>(x, W, bias, I);

    const int nlanes = Bsz * Hdim / 2;  // 32768 float2 lanes
    snn_scan_kernel<<<nlanes / SCAN_TPB, SCAN_TPB>>>(
        (const float2*)I, (float2*)spikes, (float2*)mem_final);
}

// round 15
// speedup vs baseline: 1.6300x; 1.6300x over previous
#include <cuda_runtime.h>
#include <cuda_bf16.h>

// Problem constants
#define Bsz   64
#define Tsz   512
#define Kdim  1024     // IN_DIM
#define Hdim  1024     // HID
#define Mdim  (Bsz * Tsz)   // 32768 rows of the GEMM

// exp(-1/20); compiler rounds to nearest f32, same as XLA's f64->f32 constant
#define ALPHA_F 0.95122942450071400910f
#define THRESH_F 1.0f

// Eigen gebp K-panel size (computeProductBlockingSizes caps kc at 320)
#define KC 320

// 128 MB scratch for the pre-activation currents I[b,t,h]
__device__ float g_I[(size_t)Mdim * Hdim];

// ---------------------------------------------------------------------------
// Packed f32x2 helpers. Each half of fma.rn.f32x2 / add.rn.f32x2 is an
// independent IEEE-754 fp32 fma.rn / add.rn -> bit-identical to the scalar
// ops of the validated rounding contract. (Measured R12: FFMA2 retires
// 2 FMA / ~4 SMSP-cyc = same FMA rate as scalar FFMA, but halves the issue
// slots the FMA stream occupies -> ~6% win from reduced issue pressure.)
// ---------------------------------------------------------------------------
typedef unsigned long long u64;

__device__ __forceinline__ u64 pack2(float x, float y) {
    u64 r; asm("mov.b64 %0, {%1, %2};" : "=l"(r) : "f"(x), "f"(y)); return r;
}
__device__ __forceinline__ void unpack2(u64 v, float& x, float& y) {
    asm("mov.b64 {%0, %1}, %2;" : "=f"(x), "=f"(y) : "l"(v));
}
__device__ __forceinline__ void ffma2(u64& d, u64 a, u64 b) {
    asm("fma.rn.f32x2 %0, %1, %2, %0;" : "+l"(d) : "l"(a), "l"(b));
}
__device__ __forceinline__ void fadd2(u64& d, u64 a) {
    asm("add.rn.f32x2 %0, %0, %1;" : "+l"(d) : "l"(a));
}

// ---------------------------------------------------------------------------
// GEMM: I[m,n] = sum_k x[m,k] * W[n,k] + bias[n]   ("NT", both K-contiguous)
//
// EXACT R12 GEMM (measured 1678 us). Single-buffer smem with compile-time
// addressing + register prefetch. (R13's runtime-indexed double buffer
// regressed 65% -- runtime smem indexing breaks ptxas's immediate-offset
// LDS scheduling; do not reintroduce without compile-time ping-pong.)
//
// ROUNDING CONTRACT (validated bit-exact in R9, rel_err 4e-7 -- DO NOT CHANGE):
//   per output element:
//     c0..c3 = natural-order fma chains over k-panels {0..319, 320..639,
//              640..959, 960..1023}, each starting from 0
//     total  = (((0 + c0) + c1) + c2) + c3     [plain fp32 adds, in order]
//     I      = total + bias                     [one add at the end]
// ---------------------------------------------------------------------------
#define BM 128
#define BN 128
#define BK 8
#define TM 8
#define TN 8
#define TN2 (TN / 2)
#define SPAD 4   // smem padding to kill store bank conflicts

__global__ __launch_bounds__(256, 1)
void snn_gemm_kernel(const float* __restrict__ A,      // [M, K] = x
                     const float* __restrict__ Bmat,   // [N, K] = W
                     const float* __restrict__ bias,   // [N]
                     float* __restrict__ C)            // [M, N] = I
{
    __shared__ float As[BK][BM + SPAD];
    __shared__ float Bs[BK][BN + SPAD];

    const int tid = threadIdx.x;
    const int bm  = blockIdx.y * BM;
    const int bn  = blockIdx.x * BN;

    const float* Ablk = A    + (size_t)bm * Kdim;
    const float* Bblk = Bmat + (size_t)bn * Kdim;

    // Load assignment: 2 threads per row, each loads one float4 of K.
    const int l_row = tid >> 1;           // 0..127
    const int l_col = (tid & 1) * 4;      // 0 or 4

    // Compute mapping: 16x16 thread grid; 8 rows x 8 cols per thread.
    const int tx = tid & 15;              // col group: 16 * 8 = 128 cols
    const int ty = tid >> 4;              // row group: 16 * 8 = 128 rows

    u64 acc2[TM][TN2];    // current K-panel chains (packed pairs of n)
    u64 tot2[TM][TN2];    // running sums of completed panels
#pragma unroll
    for (int i = 0; i < TM; i++)
#pragma unroll
        for (int j = 0; j < TN2; j++) { acc2[i][j] = 0ULL; tot2[i][j] = 0ULL; }

    // Prefetch tile 0 into registers.
    const float* aptr = Ablk + (size_t)l_row * Kdim + l_col;
    const float* bptr = Bblk + (size_t)l_row * Kdim + l_col;
    float4 av = *(const float4*)(aptr);
    float4 bv = *(const float4*)(bptr);

    for (int k0 = 0; k0 < Kdim; k0 += BK) {
        // Commit prefetched tile to shared memory (transposed: smem[k][row]).
        As[l_col + 0][l_row] = av.x;
        As[l_col + 1][l_row] = av.y;
        As[l_col + 2][l_row] = av.z;
        As[l_col + 3][l_row] = av.w;
        Bs[l_col + 0][l_row] = bv.x;
        Bs[l_col + 1][l_row] = bv.y;
        Bs[l_col + 2][l_row] = bv.z;
        Bs[l_col + 3][l_row] = bv.w;
        __syncthreads();

        // Prefetch next tile (latency overlaps the compute below).
        if (k0 + BK < Kdim) {
            av = *(const float4*)(aptr + k0 + BK);
            bv = *(const float4*)(bptr + k0 + BK);
        }

#pragma unroll
        for (int k = 0; k < BK; k++) {
            // A values broadcast into both packed halves.
            u64 a2[TM];
#pragma unroll
            for (int i = 0; i < TM; i++) {
                const float ar = As[k][ty * TM + i];
                a2[i] = pack2(ar, ar);
            }
            // B packed pairs: two adjacent n-columns per 64-bit load.
            u64 b2[TN2];
#pragma unroll
            for (int j = 0; j < TN2; j++)
                b2[j] = *reinterpret_cast<const u64*>(&Bs[k][tx * TN + 2 * j]);

#pragma unroll
            for (int i = 0; i < TM; i++)
#pragma unroll
                for (int j = 0; j < TN2; j++)
                    ffma2(acc2[i][j], a2[i], b2[j]);
        }

        // Fold at Eigen K-panel boundaries: k = 320, 640, 960, 1024.
        const int knext = k0 + BK;
        if (knext == KC || knext == 2 * KC || knext == 3 * KC || knext == Kdim) {
#pragma unroll
            for (int i = 0; i < TM; i++)
#pragma unroll
                for (int j = 0; j < TN2; j++) {
                    fadd2(tot2[i][j], acc2[i][j]);
                    acc2[i][j] = 0ULL;
                }
        }

        __syncthreads();   // guard smem overwrite by next iteration's stores
    }

    // Epilogue: add bias once at the end (matches reference's einsum + b).
#pragma unroll
    for (int i = 0; i < TM; i++) {
        const int row = bm + ty * TM + i;
        float* crow = C + (size_t)row * Hdim + bn + tx * TN;
        float o[TN];
#pragma unroll
        for (int j = 0; j < TN2; j++)
            unpack2(tot2[i][j], o[2 * j], o[2 * j + 1]);
#pragma unroll
        for (int j = 0; j < TN; j += 4) {
            float4 v;
            v.x = __fadd_rn(o[j + 0], bias[bn + tx * TN + j + 0]);
            v.y = __fadd_rn(o[j + 1], bias[bn + tx * TN + j + 1]);
            v.z = __fadd_rn(o[j + 2], bias[bn + tx * TN + j + 2]);
            v.w = __fadd_rn(o[j + 3], bias[bn + tx * TN + j + 3]);
            *(float4*)(crow + j) = v;
        }
    }
}

// ---------------------------------------------------------------------------
// LIF scan -- EXACT R11 version (measured 63 us). float2 lanes, unroll 8,
// plain loads, 128 threads/block. (R12's ldcs/unroll-16 variant regressed
// 4x -- streaming hints defeated ptxas load batching; do not reintroduce.)
// ROUNDING CONTRACT: separate mul/add/sub per element.
// ---------------------------------------------------------------------------
#define SCAN_TPB 128

__global__ __launch_bounds__(SCAN_TPB)
void snn_scan_kernel(const float2* __restrict__ I2,
                     float2* __restrict__ spikes2,     // [B, T, H/2]
                     float2* __restrict__ memf2)       // [B, H/2]
{
    const int gid = blockIdx.x * SCAN_TPB + threadIdx.x;  // 0 .. B*H/2-1
    const int H2  = Hdim / 2;                              // 512
    const int b   = gid >> 9;        // / H2
    const int h2  = gid & (H2 - 1);

    const size_t base = ((size_t)b * Tsz) * H2 + h2;

    float mx = 0.0f, my = 0.0f;
#pragma unroll 8
    for (int t = 0; t < Tsz; t++) {
        const float2 cur = I2[base + (size_t)t * H2];

        const float ax = __fadd_rn(__fmul_rn(ALPHA_F, mx), cur.x);
        const float ay = __fadd_rn(__fmul_rn(ALPHA_F, my), cur.y);
        const float sx = (ax >= THRESH_F) ? 1.0f : 0.0f;
        const float sy = (ay >= THRESH_F) ? 1.0f : 0.0f;

        float2 sp; sp.x = sx; sp.y = sy;
        spikes2[base + (size_t)t * H2] = sp;

        mx = __fmul_rn(ax, __fsub_rn(1.0f, sx));
        my = __fmul_rn(ay, __fsub_rn(1.0f, sy));
    }
    float2 mf; mf.x = mx; mf.y = my;
    memf2[gid] = mf;
}

// ---------------------------------------------------------------------------
// Launch
// ---------------------------------------------------------------------------
extern "C" void kernel_launch(void* const* d_in, const int* in_sizes, int n_in,
                              void* d_out, int out_size)
{
    const float* x    = (const float*)d_in[0];   // [B, T, IN]
    const float* W    = (const float*)d_in[1];   // [H, IN]
    const float* bias = (const float*)d_in[2];   // [H]

    float* out        = (float*)d_out;
    float* spikes     = out;                                  // [B,T,H]
    float* mem_final  = out + (size_t)Mdim * Hdim;            // [B,H]

    float* I;
    cudaGetSymbolAddress((void**)&I, g_I);

    dim3 ggrid(Hdim / BN, Mdim / BM);   // (8, 256)
    snn_gemm_kernel<<<ggrid, 256>>>(x, W, bias, I);

    const int nlanes = Bsz * Hdim / 2;  // 32768 float2 lanes
    snn_scan_kernel<<<nlanes / SCAN_TPB, SCAN_TPB>>>(
        (const float2*)I, (float2*)spikes, (float2*)mem_final);
}